// round 11
// baseline (speedup 1.0000x reference)
#include <cuda_runtime.h>
#include <cstdint>
#include <cstddef>

// Problem constants
#define BATCH 4
#define SEQ   2048
#define CDIM  2048
#define HDIM  128

// ---------------- scratch (allocation-free: __device__ globals) -------------
__device__ float g_q[BATCH * SEQ * HDIM];
__device__ float g_k[BATCH * SEQ * HDIM];
__device__ float g_v[BATCH * SEQ * HDIM];

// attention partials (split-KV)
#define AQT    16           // q-tiles per batch (128 rows each)
#define MAXCH  8            // max KV chunks per q-tile
__device__ float g_pacc[BATCH * AQT * MAXCH * 128 * 128];   // 33.5 MB
__device__ float g_pm[BATCH * AQT * MAXCH * 128];
__device__ float g_pl[BATCH * AQT * MAXCH * 128];

// ======================= tf32 mma helpers ===================================
__device__ __forceinline__ uint32_t f2tf32(float f) {
    uint32_t r;
    asm("cvt.rna.tf32.f32 %0, %1;" : "=r"(r) : "f"(f));
    return r;
}
__device__ __forceinline__ float tf32f(float f) {   // tf32 bits kept in a float slot
    return __uint_as_float(f2tf32(f));
}
__device__ __forceinline__ void mma_tf32(float* d, const uint32_t* a, const uint32_t* b) {
    asm volatile(
        "mma.sync.aligned.m16n8k8.row.col.f32.tf32.tf32.f32 "
        "{%0,%1,%2,%3}, {%4,%5,%6,%7}, {%8,%9}, {%0,%1,%2,%3};"
        : "+f"(d[0]), "+f"(d[1]), "+f"(d[2]), "+f"(d[3])
        : "r"(a[0]), "r"(a[1]), "r"(a[2]), "r"(a[3]), "r"(b[0]), "r"(b[1]));
}

// ======================= QKV projection v3 ==================================
// out[8192,128] = X[8192,2048] @ W[2048,128]. Block 128x128, BK=16,
// 128 threads = 4 warps (2m x 2n), warp tile 64x64 -> 128 B fragment traffic
// per MMA (tensor-bound). kappa-relabeled fragments: slot kappa=tg holds phys
// k=2tg, slot kappa=tg+4 holds phys k=2tg+1 (A and B agree -> same dot
// product). Fragments are contiguous LDS.64 from plain k-contiguous tiles.
//
// A tile (per m16 mu 0..7, ks 0..1), stride 132:
//   word(row r=h*8+g, k') = g*8 + h*64 + (k' ^ (g&4))   [bit-2 XOR swizzle]
//   -> producer STS.128 conflict-free, consumer LDS.64 conflict-free.
// B tile (per n8 nu 0..15, ks 0..1), stride 66:
//   word(k', col j) = j*8 + k'   -> consumer LDS.64 conflict-free.
#define P_NT     (CDIM / 16)     // 128 k-tiles
#define PA_TILE  132
#define PB_TILE  66
#define PA_FLOATS (16 * PA_TILE)             // 2112
#define PB_FLOATS (32 * PB_TILE)             // 2112
#define PBUF      (PA_FLOATS + PB_FLOATS)    // 4224 floats per buffer

__global__ __launch_bounds__(128, 2) void proj_kernel(
    const float* __restrict__ x,
    const float* __restrict__ Wq,
    const float* __restrict__ Wk,
    const float* __restrict__ Wv)
{
    const float* W   = (blockIdx.y == 0) ? Wq : (blockIdx.y == 1) ? Wk : Wv;
    float*       out = (blockIdx.y == 0) ? g_q : (blockIdx.y == 1) ? g_k : g_v;

    __shared__ __align__(16) float sm[2 * PBUF];   // 33.8 KB

    const int tid    = threadIdx.x;
    const int lane   = tid & 31;
    const int wid    = tid >> 5;          // 0..3
    const int warp_m = wid & 1;           // rows warp_m*64
    const int warp_n = wid >> 1;          // cols warp_n*64
    const int g      = lane >> 2;         // 0..7
    const int tg     = lane & 3;          // 0..3
    const int row0   = blockIdx.x * 128;

    // ---- A producer: thread = row tid, 4 float4 (c4 = 0..3 over 16 k) ----
    const int amu = tid >> 4;             // 0..7
    const int ah  = (tid >> 3) & 1;
    const int ag  = tid & 7;
    const float* aSrc = x + (size_t)(row0 + tid) * CDIM;
    int aW[4];
    #pragma unroll
    for (int c4 = 0; c4 < 4; c4++)
        aW[c4] = (amu * 2 + (c4 >> 1)) * PA_TILE
               + ((ag * 8 + ah * 64 + 4 * (c4 & 1)) ^ (ag & 4));

    // ---- B producer: 4 float4: row br = (tid>>5)+4*jl, col4 = tid&31 ----
    const int bcol4 = tid & 31;
    const int brb   = tid >> 5;           // 0..3
    // store base per jl (4 scalar stores each at +8e offsets in j)
    int bW[4];
    #pragma unroll
    for (int jl = 0; jl < 4; jl++) {
        const int br = brb + 4 * jl;      // 0..15
        bW[jl] = PA_FLOATS
               + ((bcol4 >> 1) * 2 + (br >> 3)) * PB_TILE
               + 32 * (bcol4 & 1) + (br & 7);     // + 8*e per element
    }

    float d[4][8][4];
    #pragma unroll
    for (int mi = 0; mi < 4; mi++)
        #pragma unroll
        for (int ni = 0; ni < 8; ni++)
            #pragma unroll
            for (int c = 0; c < 4; c++) d[mi][ni][c] = 0.f;

    // consumer fragment offsets (constant parts)
    const int aoffLo = g * 8 + ((2 * tg) ^ (g & 4));       // h=0
    const int boff   = PA_FLOATS + g * 8 + 2 * tg;

    // ---- prologue: tile 0 ----
    float4 aReg[4], bReg[4];
    #pragma unroll
    for (int c4 = 0; c4 < 4; c4++) aReg[c4] = *(const float4*)(aSrc + c4 * 4);
    #pragma unroll
    for (int jl = 0; jl < 4; jl++)
        bReg[jl] = *(const float4*)&W[(size_t)(brb + 4 * jl) * HDIM + bcol4 * 4];
    {
        float* buf = sm;
        #pragma unroll
        for (int c4 = 0; c4 < 4; c4++) {
            float* p = buf + aW[c4];
            p[0] = tf32f(aReg[c4].x); p[1] = tf32f(aReg[c4].y);
            p[2] = tf32f(aReg[c4].z); p[3] = tf32f(aReg[c4].w);
        }
        #pragma unroll
        for (int jl = 0; jl < 4; jl++) {
            float* p = buf + bW[jl];
            p[0]  = tf32f(bReg[jl].x); p[8]  = tf32f(bReg[jl].y);
            p[16] = tf32f(bReg[jl].z); p[24] = tf32f(bReg[jl].w);
        }
    }
    __syncthreads();

    for (int kt = 0; kt < P_NT; kt++) {
        const float* cur = sm + (kt & 1) * PBUF;
        float*       nxt = sm + ((kt + 1) & 1) * PBUF;
        const bool more = (kt + 1 < P_NT);

        // prefetch next tile into registers (in flight during MMAs)
        if (more) {
            const int kf = (kt + 1) * 16;
            #pragma unroll
            for (int c4 = 0; c4 < 4; c4++)
                aReg[c4] = *(const float4*)(aSrc + kf + c4 * 4);
            #pragma unroll
            for (int jl = 0; jl < 4; jl++)
                bReg[jl] = *(const float4*)
                    &W[(size_t)(kf + brb + 4 * jl) * HDIM + bcol4 * 4];
        }

        // MMAs over current buffer
        #pragma unroll
        for (int ks = 0; ks < 2; ks++) {
            uint32_t a[4][4], b[8][2];
            #pragma unroll
            for (int mi = 0; mi < 4; mi++) {
                const int toff = ((warp_m * 4 + mi) * 2 + ks) * PA_TILE;
                const float2 lo = *(const float2*)&cur[toff + aoffLo];
                const float2 hi = *(const float2*)&cur[toff + aoffLo + 64];
                a[mi][0] = __float_as_uint(lo.x);   // row g,   kappa tg
                a[mi][1] = __float_as_uint(hi.x);   // row g+8, kappa tg
                a[mi][2] = __float_as_uint(lo.y);   // row g,   kappa tg+4
                a[mi][3] = __float_as_uint(hi.y);   // row g+8, kappa tg+4
            }
            #pragma unroll
            for (int ni = 0; ni < 8; ni++) {
                const int toff = ((warp_n * 8 + ni) * 2 + ks) * PB_TILE;
                const float2 vb = *(const float2*)&cur[boff + toff];
                b[ni][0] = __float_as_uint(vb.x);
                b[ni][1] = __float_as_uint(vb.y);
            }
            #pragma unroll
            for (int mi = 0; mi < 4; mi++)
                #pragma unroll
                for (int ni = 0; ni < 8; ni++)
                    mma_tf32(d[mi][ni], a[mi], b[ni]);
        }

        // store next tile (cvt at store)
        if (more) {
            #pragma unroll
            for (int c4 = 0; c4 < 4; c4++) {
                float* p = nxt + aW[c4];
                p[0] = tf32f(aReg[c4].x); p[1] = tf32f(aReg[c4].y);
                p[2] = tf32f(aReg[c4].z); p[3] = tf32f(aReg[c4].w);
            }
            #pragma unroll
            for (int jl = 0; jl < 4; jl++) {
                float* p = nxt + bW[jl];
                p[0]  = tf32f(bReg[jl].x); p[8]  = tf32f(bReg[jl].y);
                p[16] = tf32f(bReg[jl].z); p[24] = tf32f(bReg[jl].w);
            }
        }
        __syncthreads();
    }

    // epilogue
    #pragma unroll
    for (int mi = 0; mi < 4; mi++) {
        #pragma unroll
        for (int ni = 0; ni < 8; ni++) {
            const int row = row0 + warp_m * 64 + mi * 16 + g;
            const int col = warp_n * 64 + ni * 8 + tg * 2;
            *(float2*)&out[(size_t)row * HDIM + col] =
                make_float2(d[mi][ni][0], d[mi][ni][1]);
            *(float2*)&out[(size_t)(row + 8) * HDIM + col] =
                make_float2(d[mi][ni][2], d[mi][ni][3]);
        }
    }
}

// ======================= causal flash attention (split-KV, tf32 mma) ========
// (unchanged from the 249.9 us measured version)
#define A_BM  128
#define A_BN  64
#define A_CH  4
#define QS_S  132
#define KS_S  132
#define VS_S  136
#define SS_S  68

#define ASMEM_FLOATS (128 * QS_S + 64 * KS_S + 64 * VS_S + 128 * SS_S + 3 * 128)
#define ASMEM_BYTES  (ASMEM_FLOATS * 4)

__global__ __launch_bounds__(256, 1) void attn_kernel()
{
    const int qt = blockIdx.x;          // 0..15
    const int ci = blockIdx.y;          // 0..7
    const int b  = blockIdx.z;          // 0..3

    const int ntiles = 2 * qt + 2;
    if (ci * A_CH >= ntiles) return;
    const int kt_begin = ci * A_CH;
    const int kt_end   = min(kt_begin + A_CH, ntiles);
    const int q0 = qt * A_BM;

    extern __shared__ float smem[];
    float* Qs      = smem;                       // [128][132]
    float* Ks      = Qs + 128 * QS_S;            // [64][132]
    float* Vs      = Ks + 64 * KS_S;             // [64][136]
    float* Ss      = Vs + 64 * VS_S;             // [128][68]
    float* m_s     = Ss + 128 * SS_S;            // [128]
    float* l_s     = m_s + 128;
    float* alpha_s = l_s + 128;

    const int tid    = threadIdx.x;
    const int lane   = tid & 31;
    const int wid    = tid >> 5;
    const int warp_m = wid & 3;
    const int warp_n = wid >> 2;
    const int g      = lane >> 2;
    const int tg     = lane & 3;

    const float* Qg = g_q + (size_t)b * SEQ * HDIM;
    const float* Kg = g_k + (size_t)b * SEQ * HDIM;
    const float* Vg = g_v + (size_t)b * SEQ * HDIM;

    const float scale = 0.08838834764831843f;   // 1/sqrt(128), folded into Q

    #pragma unroll
    for (int i = 0; i < 16; i++) {
        const int idx = tid + i * 256;
        const int r   = idx >> 5;
        const int c4  = idx & 31;
        const float4 v = *(const float4*)&Qg[(size_t)(q0 + r) * HDIM + c4 * 4];
        float* dst = &Qs[r * QS_S + c4 * 4];
        dst[0] = tf32f(v.x * scale); dst[1] = tf32f(v.y * scale);
        dst[2] = tf32f(v.z * scale); dst[3] = tf32f(v.w * scale);
    }
    if (tid < 128) { m_s[tid] = -1e30f; l_s[tid] = 0.f; }

    float o[2][8][4];
    #pragma unroll
    for (int mi = 0; mi < 2; mi++)
        #pragma unroll
        for (int ni = 0; ni < 8; ni++)
            #pragma unroll
            for (int c = 0; c < 4; c++) o[mi][ni][c] = 0.f;

    __syncthreads();

    for (int kt = kt_begin; kt < kt_end; kt++) {
        const int k0 = kt * A_BN;
        #pragma unroll
        for (int i = 0; i < 8; i++) {
            const int idx = tid + i * 256;
            const int r   = idx >> 5;
            const int c4  = idx & 31;
            const float4 kv = *(const float4*)&Kg[(size_t)(k0 + r) * HDIM + c4 * 4];
            float* kd = &Ks[r * KS_S + c4 * 4];
            kd[0] = tf32f(kv.x); kd[1] = tf32f(kv.y);
            kd[2] = tf32f(kv.z); kd[3] = tf32f(kv.w);
            const float4 vv = *(const float4*)&Vg[(size_t)(k0 + r) * HDIM + c4 * 4];
            float* vd = &Vs[r * VS_S + c4 * 4];
            vd[0] = tf32f(vv.x); vd[1] = tf32f(vv.y);
            vd[2] = tf32f(vv.z); vd[3] = tf32f(vv.w);
        }
        __syncthreads();

        float s[2][4][4];
        #pragma unroll
        for (int mi = 0; mi < 2; mi++)
            #pragma unroll
            for (int ni = 0; ni < 4; ni++)
                #pragma unroll
                for (int c = 0; c < 4; c++) s[mi][ni][c] = 0.f;

        #pragma unroll
        for (int ks = 0; ks < 16; ks++) {
            const int kb = ks * 8;
            uint32_t a[2][4], kbf[4][2];
            #pragma unroll
            for (int mi = 0; mi < 2; mi++) {
                const int rb = warp_m * 32 + mi * 16;
                a[mi][0] = __float_as_uint(Qs[(rb + g)     * QS_S + kb + tg]);
                a[mi][1] = __float_as_uint(Qs[(rb + 8 + g) * QS_S + kb + tg]);
                a[mi][2] = __float_as_uint(Qs[(rb + g)     * QS_S + kb + 4 + tg]);
                a[mi][3] = __float_as_uint(Qs[(rb + 8 + g) * QS_S + kb + 4 + tg]);
            }
            #pragma unroll
            for (int ni = 0; ni < 4; ni++) {
                const int key = warp_n * 32 + ni * 8 + g;
                kbf[ni][0] = __float_as_uint(Ks[key * KS_S + kb + tg]);
                kbf[ni][1] = __float_as_uint(Ks[key * KS_S + kb + 4 + tg]);
            }
            #pragma unroll
            for (int mi = 0; mi < 2; mi++)
                #pragma unroll
                for (int ni = 0; ni < 4; ni++)
                    mma_tf32(s[mi][ni], a[mi], kbf[ni]);
        }

        const bool diag = (k0 + A_BN - 1 > q0);
        #pragma unroll
        for (int mi = 0; mi < 2; mi++) {
            #pragma unroll
            for (int ni = 0; ni < 4; ni++) {
                const int r0  = warp_m * 32 + mi * 16 + g;
                const int col = warp_n * 32 + ni * 8 + tg * 2;
                float c0 = s[mi][ni][0], c1 = s[mi][ni][1];
                float c2 = s[mi][ni][2], c3 = s[mi][ni][3];
                if (diag) {
                    const int kc = k0 + col, qa = q0 + r0, qb = qa + 8;
                    if (kc     > qa) c0 = -1e30f;
                    if (kc + 1 > qa) c1 = -1e30f;
                    if (kc     > qb) c2 = -1e30f;
                    if (kc + 1 > qb) c3 = -1e30f;
                }
                *(float2*)&Ss[r0 * SS_S + col]       = make_float2(c0, c1);
                *(float2*)&Ss[(r0 + 8) * SS_S + col] = make_float2(c2, c3);
            }
        }
        __syncthreads();

        #pragma unroll
        for (int rr = 0; rr < 16; rr++) {
            const int row = wid * 16 + rr;
            float x0 = Ss[row * SS_S + lane];
            float x1 = Ss[row * SS_S + 32 + lane];
            float mx = fmaxf(x0, x1);
            #pragma unroll
            for (int off = 16; off > 0; off >>= 1)
                mx = fmaxf(mx, __shfl_xor_sync(0xFFFFFFFFu, mx, off));
            const float m_old = m_s[row];
            const float m_new = fmaxf(m_old, mx);
            const float e0 = __expf(x0 - m_new);
            const float e1 = __expf(x1 - m_new);
            Ss[row * SS_S + lane]      = __uint_as_float(f2tf32(e0));
            Ss[row * SS_S + 32 + lane] = __uint_as_float(f2tf32(e1));
            float sum = e0 + e1;
            #pragma unroll
            for (int off = 16; off > 0; off >>= 1)
                sum += __shfl_xor_sync(0xFFFFFFFFu, sum, off);
            if (lane == 0) {
                const float alpha = __expf(m_old - m_new);
                alpha_s[row] = alpha;
                l_s[row]     = l_s[row] * alpha + sum;
                m_s[row]     = m_new;
            }
        }
        __syncthreads();

        #pragma unroll
        for (int mi = 0; mi < 2; mi++) {
            const float al0 = alpha_s[warp_m * 32 + mi * 16 + g];
            const float al1 = alpha_s[warp_m * 32 + mi * 16 + 8 + g];
            #pragma unroll
            for (int ni = 0; ni < 8; ni++) {
                o[mi][ni][0] *= al0; o[mi][ni][1] *= al0;
                o[mi][ni][2] *= al1; o[mi][ni][3] *= al1;
            }
        }
        #pragma unroll
        for (int ks = 0; ks < 8; ks++) {
            const int kb = ks * 8;
            uint32_t a[2][4], vb[8][2];
            #pragma unroll
            for (int mi = 0; mi < 2; mi++) {
                const int rb = warp_m * 32 + mi * 16;
                a[mi][0] = __float_as_uint(Ss[(rb + g)     * SS_S + kb + tg]);
                a[mi][1] = __float_as_uint(Ss[(rb + 8 + g) * SS_S + kb + tg]);
                a[mi][2] = __float_as_uint(Ss[(rb + g)     * SS_S + kb + 4 + tg]);
                a[mi][3] = __float_as_uint(Ss[(rb + 8 + g) * SS_S + kb + 4 + tg]);
            }
            #pragma unroll
            for (int ni = 0; ni < 8; ni++) {
                const int col = warp_n * 64 + ni * 8 + g;
                vb[ni][0] = __float_as_uint(Vs[(kb + tg)     * VS_S + col]);
                vb[ni][1] = __float_as_uint(Vs[(kb + 4 + tg) * VS_S + col]);
            }
            #pragma unroll
            for (int mi = 0; mi < 2; mi++)
                #pragma unroll
                for (int ni = 0; ni < 8; ni++)
                    mma_tf32(o[mi][ni], a[mi], vb[ni]);
        }
        __syncthreads();
    }

    const int slot = (b * AQT + qt) * MAXCH + ci;
    float* pbase = g_pacc + (size_t)slot * (128 * 128);
    #pragma unroll
    for (int mi = 0; mi < 2; mi++) {
        #pragma unroll
        for (int ni = 0; ni < 8; ni++) {
            const int row = warp_m * 32 + mi * 16 + g;
            const int col = warp_n * 64 + ni * 8 + tg * 2;
            *(float2*)&pbase[row * 128 + col] =
                make_float2(o[mi][ni][0], o[mi][ni][1]);
            *(float2*)&pbase[(row + 8) * 128 + col] =
                make_float2(o[mi][ni][2], o[mi][ni][3]);
        }
    }
    if (tid < 128) {
        g_pm[slot * 128 + tid] = m_s[tid];
        g_pl[slot * 128 + tid] = l_s[tid];
    }
}

// ======================= combine partials ===================================
__global__ __launch_bounds__(256) void combine_kernel(float* __restrict__ out)
{
    const int qt = blockIdx.x;
    const int b  = blockIdx.y;
    const int nch = (2 * qt + 5) >> 2;
    const int slot0 = (b * AQT + qt) * MAXCH;
    const int q0 = qt * A_BM;

    __shared__ float w[MAXCH][128];

    const int tid = threadIdx.x;
    if (tid < 128) {
        const int row = tid;
        float M = -1e30f;
        for (int i = 0; i < nch; i++)
            M = fmaxf(M, g_pm[(slot0 + i) * 128 + row]);
        float L = 0.f;
        for (int i = 0; i < nch; i++)
            L += g_pl[(slot0 + i) * 128 + row] *
                 __expf(g_pm[(slot0 + i) * 128 + row] - M);
        const float invL = 1.f / L;
        for (int i = 0; i < nch; i++)
            w[i][row] = __expf(g_pm[(slot0 + i) * 128 + row] - M) * invL;
    }
    __syncthreads();

    const int c4    = (tid & 31) * 4;
    const int rbase = (tid >> 5) * 16;
    #pragma unroll
    for (int rr = 0; rr < 16; rr++) {
        const int row = rbase + rr;
        float4 o = make_float4(0.f, 0.f, 0.f, 0.f);
        for (int i = 0; i < nch; i++) {
            const float4 pa = *(const float4*)
                &g_pacc[(size_t)(slot0 + i) * (128 * 128) + row * 128 + c4];
            const float wi = w[i][row];
            o.x += wi * pa.x; o.y += wi * pa.y;
            o.z += wi * pa.z; o.w += wi * pa.w;
        }
        *(float4*)&out[((size_t)b * SEQ + q0 + row) * HDIM + c4] = o;
    }
}

// ======================= launch =============================================
extern "C" void kernel_launch(void* const* d_in, const int* in_sizes, int n_in,
                              void* d_out, int out_size)
{
    const float* x  = (const float*)d_in[0];
    const float* Wq = (const float*)d_in[1];
    const float* Wk = (const float*)d_in[2];
    const float* Wv = (const float*)d_in[3];
    float* out = (float*)d_out;

    static bool attr_set = false;
    if (!attr_set) {
        cudaFuncSetAttribute(attn_kernel,
                             cudaFuncAttributeMaxDynamicSharedMemorySize,
                             ASMEM_BYTES);
        attr_set = true;
    }

    // QKV projections: 64 M-tiles x 3 weights = 192 CTAs, 128 threads
    dim3 pgrid(BATCH * SEQ / 128, 3);
    proj_kernel<<<pgrid, 128>>>(x, Wq, Wk, Wv);

    // attention chunks
    dim3 agrid(AQT, MAXCH, BATCH);
    attn_kernel<<<agrid, 256, ASMEM_BYTES>>>();

    // combine
    dim3 cgrid(AQT, BATCH);
    combine_kernel<<<cgrid, 256>>>(out);
}